// round 4
// baseline (speedup 1.0000x reference)
#include <cuda_runtime.h>
#include <cstdint>

#define BB  4
#define N0  16384
#define S1V 2048
#define S2V 1024
#define KK  32

// ---------------- device scratch (no allocations allowed) ----------------
__device__ __align__(16) float g_xyz0 [BB * N0  * 3];
__device__ __align__(16) float g_feat0[BB * N0  * 3];
__device__ __align__(16) float g_xyz1 [BB * S1V * 3];
__device__ __align__(16) float g_xyz2 [BB * S2V * 3];
__device__ int   g_fidx1[BB * S1V];
__device__ int   g_fidx2[BB * S2V];
__device__ int   g_nidx1[BB * S1V * KK];
__device__ int   g_nidx2[BB * S2V * KK];
__device__ __align__(16) float g_feat1[BB * S1V * 32];
__device__ __align__(16) float g_bufA [8388608];   // [b][c][s*K+k] channel-major
__device__ __align__(16) float g_bufB [8388608];
__device__ float g_sum[6 * BB * 64];
__device__ float g_sq [6 * BB * 64];

// ---------------- helpers ----------------
__device__ __forceinline__ unsigned fkey(float f) {
    unsigned u = __float_as_uint(f);
    return u ^ (((unsigned)((int)u >> 31)) | 0x80000000u);
}
__device__ __forceinline__ unsigned long long ullmin2(unsigned long long a, unsigned long long b){return a<b?a:b;}
__device__ __forceinline__ unsigned long long ullmax2(unsigned long long a, unsigned long long b){return a>b?a:b;}

// ---------------- zero stats ----------------
__global__ void k_zero() {
    int t = blockIdx.x * blockDim.x + threadIdx.x;
    if (t < 6 * BB * 64) { g_sum[t] = 0.f; g_sq[t] = 0.f; }
}

// ---------------- transpose [B,3,N] -> [B,N,3] + copy pc to out ----------------
__global__ void k_transpose(const float* __restrict__ pc, const float* __restrict__ feat,
                            float* __restrict__ out_pc) {
    int i = blockIdx.x * blockDim.x + threadIdx.x;
    if (i < BB * 3 * N0) {
        int b = i / (3 * N0);
        int c = (i / N0) % 3;
        int n = i % N0;
        float v = pc[i];
        g_xyz0 [(b * N0 + n) * 3 + c] = v;
        g_feat0[(b * N0 + n) * 3 + c] = feat[i];
        out_pc[i] = v;
    }
}

// ---------------- farthest point sampling ----------------
// Argmax with 1-ulp tie window: any point whose dist is within 1 ulp of the
// exact block max is treated as tied; lowest index wins (mirrors XLA argmax
// first-index semantics under its own rounding of the distance).
template <int N, int S>
__global__ void k_fps(const float* __restrict__ xyz, int* __restrict__ fidx,
                      float* __restrict__ sel_xyz,   // [b][s][3]
                      float* __restrict__ out_pc,    // [b][3][S]
                      float* __restrict__ out_fidx)  // [b][S] as float
{
    extern __shared__ float sm[];
    float* sx = sm;
    float* sy = sm + N;
    float* sz = sm + 2 * N;
    __shared__ float swmax[32];
    __shared__ float s_gmax;
    __shared__ int   s_argidx;
    __shared__ float s_cx, s_cy, s_cz;

    const int tid = threadIdx.x;
    const int b = blockIdx.x;
    const float* base = xyz + (size_t)b * N * 3;
    constexpr int P = N / 1024;

    float dist[P];
#pragma unroll
    for (int j = 0; j < P; j++) {
        int p = tid + j * 1024;
        sx[p] = base[p * 3 + 0];
        sy[p] = base[p * 3 + 1];
        sz[p] = base[p * 3 + 2];
        dist[j] = 1e10f;
    }
    __syncthreads();

    int far = 0;
    for (int i = 0; i < S; i++) {
        if (tid == 0) {
            fidx[b * S + i] = far;
            s_cx = sx[far]; s_cy = sy[far]; s_cz = sz[far];
        }
        __syncthreads();                               // A
        float cx = s_cx, cy = s_cy, cz = s_cz;
        float mval = -1.f;
#pragma unroll
        for (int j = 0; j < P; j++) {
            int p = tid + j * 1024;
            float dx = sx[p] - cx;
            float dy = sy[p] - cy;
            float dz = sz[p] - cz;
            // XLA left-fold contracted reduce: fma(dz,dz, fma(dy,dy, dx*dx))
            float d = fmaf(dz, dz, fmaf(dy, dy, __fmul_rn(dx, dx)));
            float nd = fminf(dist[j], d);
            dist[j] = nd;
            mval = fmaxf(mval, nd);
        }
#pragma unroll
        for (int o = 16; o; o >>= 1) mval = fmaxf(mval, __shfl_down_sync(0xffffffffu, mval, o));
        if ((tid & 31) == 0) swmax[tid >> 5] = mval;
        __syncthreads();                               // B
        if (tid == 64) s_argidx = 0x7fffffff;
        if (tid < 32) {
            float v = swmax[tid];
#pragma unroll
            for (int o = 16; o; o >>= 1) v = fmaxf(v, __shfl_down_sync(0xffffffffu, v, o));
            if (tid == 0) s_gmax = v;
        }
        __syncthreads();                               // C
        const unsigned gbits = __float_as_uint(s_gmax);
#pragma unroll
        for (int j = 0; j < P; j++) {
            // dist >= 0 and dist <= g, so bit patterns are monotone:
            // accept exact max and 1-ulp-below (rounding-ambiguous ties)
            if (gbits - __float_as_uint(dist[j]) <= 1u)
                atomicMin(&s_argidx, tid + j * 1024);
        }
        __syncthreads();                               // D
        far = s_argidx;
    }
    __syncthreads();
    for (int i = tid; i < S; i += 1024) {
        int f = fidx[b * S + i];
        float x = sx[f], y = sy[f], z = sz[f];
        sel_xyz[(b * S + i) * 3 + 0] = x;
        sel_xyz[(b * S + i) * 3 + 1] = y;
        sel_xyz[(b * S + i) * 3 + 2] = z;
        out_pc[b * 3 * S + 0 * S + i] = x;
        out_pc[b * 3 * S + 1 * S + i] = y;
        out_pc[b * 3 * S + 2 * S + i] = z;
        out_fidx[b * S + i] = (float)f;
    }
}

// ---------------- kNN (k=32) ----------------
template <int N, int S>
__global__ void k_knn(const float* __restrict__ q, const float* __restrict__ ref,
                      int* __restrict__ nidx)
{
    constexpr int T = 256;
    constexpr int P = N / T;
    constexpr int CAP = 8;
    const int tid = threadIdx.x;
    const int gq = blockIdx.x;
    const int b = gq / S, s = gq % S;

    const float qx = q[(b * S + s) * 3 + 0];
    const float qy = q[(b * S + s) * 3 + 1];
    const float qz = q[(b * S + s) * 3 + 2];
    // XLA left-fold contracted: fma(qz,qz, fma(qy,qy, qx*qx))
    const float qq = fmaf(qz, qz, fmaf(qy, qy, __fmul_rn(qx, qx)));

    unsigned long long k[CAP];
#pragma unroll
    for (int t = 0; t < CAP; t++) k[t] = ~0ull;

    const float* rb = ref + (size_t)b * N * 3;
#pragma unroll 4
    for (int j = 0; j < P; j++) {
        int i = tid + j * T;
        float rx = rb[i * 3 + 0];
        float ry = rb[i * 3 + 1];
        float rz = rb[i * 3 + 2];
        float dot = fmaf(qz, rz, fmaf(qy, ry, __fmul_rn(qx, rx)));
        float rr  = fmaf(rz, rz, fmaf(ry, ry, __fmul_rn(rx, rx)));
        float d = __fadd_rn(__fsub_rn(qq, __fmul_rn(2.f, dot)), rr);
        unsigned long long key = ((unsigned long long)fkey(d) << 32) | (unsigned)i;
        if (key < k[CAP - 1]) {
#pragma unroll
            for (int t = CAP - 1; t > 0; t--) k[t] = ullmax2(k[t - 1], ullmin2(k[t], key));
            k[0] = ullmin2(k[0], key);
        }
    }

    __shared__ unsigned long long swmin[8];
    __shared__ unsigned long long s_best;
    for (int kk = 0; kk < KK; kk++) {
        unsigned long long m = k[0];
#pragma unroll
        for (int t = 1; t < CAP; t++) m = ullmin2(m, k[t]);
#pragma unroll
        for (int o = 16; o; o >>= 1) m = ullmin2(m, __shfl_down_sync(0xffffffffu, m, o));
        if ((tid & 31) == 0) swmin[tid >> 5] = m;
        __syncthreads();
        if (tid < 32) {
            unsigned long long v = (tid < 8) ? swmin[tid] : ~0ull;
#pragma unroll
            for (int o = 4; o; o >>= 1) v = ullmin2(v, __shfl_down_sync(0xffffffffu, v, o));
            if (tid == 0) s_best = v;
        }
        __syncthreads();
        unsigned long long best = s_best;
        if (tid == 0) nidx[((size_t)(b * S + s)) * KK + kk] = (int)(unsigned)(best & 0xffffffffu);
#pragma unroll
        for (int t = 0; t < CAP; t++) if (k[t] == best) k[t] = ~0ull;
        __syncthreads();
    }
}

// ---------------- gather + first 1x1 conv + stats ----------------
template <int FDIM, int COUT, int SS, int NREF>
__global__ void k_gather_mm(const float* __restrict__ refxyz,
                            const float* __restrict__ reffeat,
                            const float* __restrict__ newxyz,
                            const int* __restrict__ nidx,
                            const float* __restrict__ W,
                            float* __restrict__ y,
                            float* __restrict__ sum, float* __restrict__ sq)
{
    constexpr int CIN = 3 + FDIM;
    __shared__ float sW[CIN * COUT];
    for (int i = threadIdx.x; i < CIN * COUT; i += blockDim.x) sW[i] = W[i];
    __syncthreads();

    int r = blockIdx.x * blockDim.x + threadIdx.x;
    int b = r / (SS * KK);
    int rem = r - b * (SS * KK);
    int s = rem / KK;
    int n = nidx[r];

    float in[CIN];
#pragma unroll
    for (int c = 0; c < 3; c++)
        in[c] = refxyz[((size_t)(b * NREF + n)) * 3 + c] - newxyz[((size_t)(b * SS + s)) * 3 + c];
#pragma unroll
    for (int j = 0; j < FDIM; j++)
        in[3 + j] = reffeat[((size_t)(b * NREF + n)) * FDIM + j];

    float acc[COUT];
#pragma unroll
    for (int c = 0; c < COUT; c++) acc[c] = 0.f;
#pragma unroll
    for (int j = 0; j < CIN; j++) {
        float v = in[j];
#pragma unroll
        for (int c = 0; c < COUT; c++) acc[c] = fmaf(v, sW[j * COUT + c], acc[c]);
    }
#pragma unroll
    for (int c = 0; c < COUT; c++)
        y[((size_t)(b * COUT + c)) * (SS * KK) + rem] = acc[c];

    int lane = threadIdx.x & 31;
#pragma unroll
    for (int c = 0; c < COUT; c++) {
        float v = acc[c], v2 = v * v;
#pragma unroll
        for (int o = 16; o; o >>= 1) {
            v  += __shfl_down_sync(0xffffffffu, v,  o);
            v2 += __shfl_down_sync(0xffffffffu, v2, o);
        }
        if (lane == 0) { atomicAdd(&sum[b * 64 + c], v); atomicAdd(&sq[b * 64 + c], v2); }
    }
}

// ---------------- instance-norm + relu + 1x1 conv + stats ----------------
template <int CIN, int COUT, int SS>
__global__ void k_mm(const float* __restrict__ x, const float* __restrict__ W,
                     const float* __restrict__ sumIn, const float* __restrict__ sqIn,
                     float* __restrict__ y,
                     float* __restrict__ sumOut, float* __restrict__ sqOut)
{
    __shared__ float sW[CIN * COUT];
    __shared__ float sMu[CIN], sInv[CIN];
    int r = blockIdx.x * blockDim.x + threadIdx.x;
    int b = r / (SS * KK);
    int rem = r - b * (SS * KK);
    for (int i = threadIdx.x; i < CIN * COUT; i += blockDim.x) sW[i] = W[i];
    if (threadIdx.x < CIN) {
        float cnt = (float)(SS * KK);
        float mu = sumIn[b * 64 + threadIdx.x] / cnt;
        float var = sqIn[b * 64 + threadIdx.x] / cnt - mu * mu;
        sMu[threadIdx.x] = mu;
        sInv[threadIdx.x] = rsqrtf(var + 1e-5f);
    }
    __syncthreads();

    float acc[COUT];
#pragma unroll
    for (int c = 0; c < COUT; c++) acc[c] = 0.f;
#pragma unroll
    for (int j = 0; j < CIN; j++) {
        float v = x[((size_t)(b * CIN + j)) * (SS * KK) + rem];
        v = fmaxf(0.f, (v - sMu[j]) * sInv[j]);
#pragma unroll
        for (int c = 0; c < COUT; c++) acc[c] = fmaf(v, sW[j * COUT + c], acc[c]);
    }
#pragma unroll
    for (int c = 0; c < COUT; c++)
        y[((size_t)(b * COUT + c)) * (SS * KK) + rem] = acc[c];

    int lane = threadIdx.x & 31;
#pragma unroll
    for (int c = 0; c < COUT; c++) {
        float v = acc[c], v2 = v * v;
#pragma unroll
        for (int o = 16; o; o >>= 1) {
            v  += __shfl_down_sync(0xffffffffu, v,  o);
            v2 += __shfl_down_sync(0xffffffffu, v2, o);
        }
        if (lane == 0) { atomicAdd(&sumOut[b * 64 + c], v); atomicAdd(&sqOut[b * 64 + c], v2); }
    }
}

// ---------------- instance-norm + relu + maxpool over K ----------------
template <int C, int SS, bool CHMAJOR>
__global__ void k_maxpool(const float* __restrict__ x,
                          const float* __restrict__ sumIn, const float* __restrict__ sqIn,
                          float* __restrict__ outp)
{
    int t = blockIdx.x * blockDim.x + threadIdx.x;   // over B*C*SS
    int s = t % SS;
    int c = (t / SS) % C;
    int b = t / (SS * C);
    float cnt = (float)(SS * KK);
    float mu = sumIn[b * 64 + c] / cnt;
    float var = sqIn[b * 64 + c] / cnt - mu * mu;
    float inv = rsqrtf(var + 1e-5f);

    const float4* p = reinterpret_cast<const float4*>(
        x + ((size_t)(b * C + c)) * (SS * KK) + (size_t)s * KK);
    float m = -3.4e38f;
#pragma unroll
    for (int qv = 0; qv < KK / 4; qv++) {
        float4 v = p[qv];
        m = fmaxf(m, fmaxf(fmaxf(v.x, v.y), fmaxf(v.z, v.w)));
    }
    // norm (inv>0) and relu are monotone: max(relu(norm(v))) == relu(norm(max v))
    float outv = fmaxf(0.f, (m - mu) * inv);
    if (CHMAJOR) outp[(b * C + c) * SS + s] = outv;
    else         outp[(b * SS + s) * C + c] = outv;
}

// ---------------- launch ----------------
extern "C" void kernel_launch(void* const* d_in, const int* in_sizes, int n_in,
                              void* d_out, int out_size)
{
    const float* pc     = (const float*)d_in[0];
    const float* feat   = (const float*)d_in[1];
    const float* sa1_w1 = (const float*)d_in[2];
    const float* sa1_w2 = (const float*)d_in[3];
    const float* sa1_w3 = (const float*)d_in[4];
    const float* sa2_w1 = (const float*)d_in[5];
    const float* sa2_w2 = (const float*)d_in[6];
    const float* sa2_w3 = (const float*)d_in[7];

    float* out = (float*)d_out;
    float* out_pc      = out;                       // 4*3*16384
    float* out_pc_l1   = out + 196608;              // 4*3*2048
    float* out_pc_l2   = out + 196608 + 24576;      // 4*3*1024
    float* out_feat_l2 = out + 196608 + 24576 + 12288;          // 4*64*1024
    float* out_fidx1   = out + 196608 + 24576 + 12288 + 262144; // 4*2048
    float* out_fidx2   = out + 196608 + 24576 + 12288 + 262144 + 8192; // 4*1024

    // device symbol addresses
    float *xyz0, *feat0, *xyz1, *xyz2, *feat1, *bufA, *bufB, *sum, *sq;
    int *fidx1, *fidx2, *nidx1, *nidx2;
    cudaGetSymbolAddress((void**)&xyz0,  g_xyz0);
    cudaGetSymbolAddress((void**)&feat0, g_feat0);
    cudaGetSymbolAddress((void**)&xyz1,  g_xyz1);
    cudaGetSymbolAddress((void**)&xyz2,  g_xyz2);
    cudaGetSymbolAddress((void**)&feat1, g_feat1);
    cudaGetSymbolAddress((void**)&bufA,  g_bufA);
    cudaGetSymbolAddress((void**)&bufB,  g_bufB);
    cudaGetSymbolAddress((void**)&sum,   g_sum);
    cudaGetSymbolAddress((void**)&sq,    g_sq);
    cudaGetSymbolAddress((void**)&fidx1, g_fidx1);
    cudaGetSymbolAddress((void**)&fidx2, g_fidx2);
    cudaGetSymbolAddress((void**)&nidx1, g_nidx1);
    cudaGetSymbolAddress((void**)&nidx2, g_nidx2);

    // opt-in shared memory for FPS stage 1 (192 KB)
    cudaFuncSetAttribute((const void*)k_fps<N0, S1V>,
                         cudaFuncAttributeMaxDynamicSharedMemorySize, 3 * N0 * 4);
    cudaFuncSetAttribute((const void*)k_fps<S1V, S2V>,
                         cudaFuncAttributeMaxDynamicSharedMemorySize, 3 * S1V * 4);

    k_zero<<<6, 256>>>();
    k_transpose<<<768, 256>>>(pc, feat, out_pc);

    // ---- stage 1 ----
    k_fps<N0, S1V><<<BB, 1024, 3 * N0 * 4>>>(xyz0, fidx1, xyz1, out_pc_l1, out_fidx1);
    k_knn<N0, S1V><<<BB * S1V, 256>>>(xyz1, xyz0, nidx1);
    k_gather_mm<3, 32, S1V, N0><<<(BB * S1V * KK) / 256, 256>>>(
        xyz0, feat0, xyz1, nidx1, sa1_w1, bufA, sum + 0 * BB * 64, sq + 0 * BB * 64);
    k_mm<32, 32, S1V><<<(BB * S1V * KK) / 256, 256>>>(
        bufA, sa1_w2, sum + 0 * BB * 64, sq + 0 * BB * 64, bufB,
        sum + 1 * BB * 64, sq + 1 * BB * 64);
    k_mm<32, 32, S1V><<<(BB * S1V * KK) / 256, 256>>>(
        bufB, sa1_w3, sum + 1 * BB * 64, sq + 1 * BB * 64, bufA,
        sum + 2 * BB * 64, sq + 2 * BB * 64);
    k_maxpool<32, S1V, false><<<(BB * 32 * S1V) / 256, 256>>>(
        bufA, sum + 2 * BB * 64, sq + 2 * BB * 64, feat1);   // point-major [b][s][32]

    // ---- stage 2 ----
    k_fps<S1V, S2V><<<BB, 1024, 3 * S1V * 4>>>(xyz1, fidx2, xyz2, out_pc_l2, out_fidx2);
    k_knn<S1V, S2V><<<BB * S2V, 256>>>(xyz2, xyz1, nidx2);
    k_gather_mm<32, 64, S2V, S1V><<<(BB * S2V * KK) / 256, 256>>>(
        xyz1, feat1, xyz2, nidx2, sa2_w1, bufA, sum + 3 * BB * 64, sq + 3 * BB * 64);
    k_mm<64, 64, S2V><<<(BB * S2V * KK) / 256, 256>>>(
        bufA, sa2_w2, sum + 3 * BB * 64, sq + 3 * BB * 64, bufB,
        sum + 4 * BB * 64, sq + 4 * BB * 64);
    k_mm<64, 64, S2V><<<(BB * S2V * KK) / 256, 256>>>(
        bufB, sa2_w3, sum + 4 * BB * 64, sq + 4 * BB * 64, bufA,
        sum + 5 * BB * 64, sq + 5 * BB * 64);
    k_maxpool<64, S2V, true><<<(BB * 64 * S2V) / 256, 256>>>(
        bufA, sum + 5 * BB * 64, sq + 5 * BB * 64, out_feat_l2); // channel-major
}

// round 5
// speedup vs baseline: 1.1040x; 1.1040x over previous
#include <cuda_runtime.h>
#include <cstdint>

#define BB  4
#define N0  16384
#define S1V 2048
#define S2V 1024
#define KK  32

// ---------------- device scratch (no allocations allowed) ----------------
__device__ __align__(16) float g_xyz0 [BB * N0  * 3];
__device__ __align__(16) float g_feat0[BB * N0  * 3];
__device__ __align__(16) float g_xyz1 [BB * S1V * 3];
__device__ __align__(16) float g_xyz2 [BB * S2V * 3];
__device__ int   g_fidx1[BB * S1V];
__device__ int   g_fidx2[BB * S2V];
__device__ int   g_nidx1[BB * S1V * KK];
__device__ int   g_nidx2[BB * S2V * KK];
__device__ __align__(16) float g_feat1[BB * S1V * 32];
__device__ __align__(16) float g_bufA [8388608];   // [b][c][s*K+k] channel-major
__device__ __align__(16) float g_bufB [8388608];
__device__ float g_sum[6 * BB * 64];
__device__ float g_sq [6 * BB * 64];

// ---------------- helpers ----------------
__device__ __forceinline__ unsigned fkey(float f) {
    unsigned u = __float_as_uint(f);
    return u ^ (((unsigned)((int)u >> 31)) | 0x80000000u);
}
__device__ __forceinline__ unsigned long long ullmin2(unsigned long long a, unsigned long long b){return a<b?a:b;}
__device__ __forceinline__ unsigned long long ullmax2(unsigned long long a, unsigned long long b){return a>b?a:b;}

// ---------------- zero stats ----------------
__global__ void k_zero() {
    int t = blockIdx.x * blockDim.x + threadIdx.x;
    if (t < 6 * BB * 64) { g_sum[t] = 0.f; g_sq[t] = 0.f; }
}

// ---------------- transpose [B,3,N] -> [B,N,3] + copy pc to out ----------------
__global__ void k_transpose(const float* __restrict__ pc, const float* __restrict__ feat,
                            float* __restrict__ out_pc) {
    int i = blockIdx.x * blockDim.x + threadIdx.x;
    if (i < BB * 3 * N0) {
        int b = i / (3 * N0);
        int c = (i / N0) % 3;
        int n = i % N0;
        float v = pc[i];
        g_xyz0 [(b * N0 + n) * 3 + c] = v;
        g_feat0[(b * N0 + n) * 3 + c] = feat[i];
        out_pc[i] = v;
    }
}

// ---------------- farthest point sampling ----------------
// Distance form (fmaf chain) and 1-ulp tie window + min-index are LOAD-BEARING
// for bit-compat with the XLA reference — do not alter.
// 3 barriers/iter; exact max via atomicMax on float bits (dist >= 0).
template <int N, int S>
__global__ void k_fps(const float* __restrict__ xyz, int* __restrict__ fidx,
                      float* __restrict__ sel_xyz,   // [b][s][3]
                      float* __restrict__ out_pc,    // [b][3][S]
                      float* __restrict__ out_fidx)  // [b][S] as float
{
    extern __shared__ float sm[];
    float2* sxy = (float2*)sm;        // N x (x,y)
    float*  szp = sm + 2 * N;         // N x z
    __shared__ unsigned s_maxbits;
    __shared__ int      s_argidx;
    __shared__ float    s_cx, s_cy, s_cz;

    const int tid = threadIdx.x;
    const int b = blockIdx.x;
    const float* base = xyz + (size_t)b * N * 3;
    constexpr int P = N / 1024;

    float dist[P];
#pragma unroll
    for (int j = 0; j < P; j++) {
        int p = tid + j * 1024;
        float x = base[p * 3 + 0];
        float y = base[p * 3 + 1];
        float z = base[p * 3 + 2];
        sxy[p] = make_float2(x, y);
        szp[p] = z;
        dist[j] = 1e10f;
    }
    __syncthreads();

    int far = 0;
    for (int i = 0; i < S; i++) {
        if (tid == 0) {
            fidx[b * S + i] = far;
            float2 c = sxy[far];
            s_cx = c.x; s_cy = c.y; s_cz = szp[far];
            s_maxbits = 0u;
            s_argidx  = 0x7fffffff;
        }
        __syncthreads();                               // 1: centroid visible, resets done
        const float cx = s_cx, cy = s_cy, cz = s_cz;
        float mval = 0.f;
#pragma unroll
        for (int j = 0; j < P; j++) {
            int p = tid + j * 1024;
            float2 xy = sxy[p];
            float dx = xy.x - cx;
            float dy = xy.y - cy;
            float dz = szp[p] - cz;
            // XLA left-fold contracted reduce: fma(dz,dz, fma(dy,dy, dx*dx))
            float d = fmaf(dz, dz, fmaf(dy, dy, __fmul_rn(dx, dx)));
            float nd = fminf(dist[j], d);
            dist[j] = nd;
            mval = fmaxf(mval, nd);
        }
#pragma unroll
        for (int o = 16; o; o >>= 1) mval = fmaxf(mval, __shfl_xor_sync(0xffffffffu, mval, o));
        if ((tid & 31) == 0) atomicMax(&s_maxbits, __float_as_uint(mval));
        __syncthreads();                               // 2: global max final
        const unsigned gbits = s_maxbits;
#pragma unroll
        for (int j = 0; j < P; j++) {
            // dist >= 0 -> bits monotone; accept exact max and 1 ulp below
            if (gbits - __float_as_uint(dist[j]) <= 1u)
                atomicMin(&s_argidx, tid + j * 1024);
        }
        __syncthreads();                               // 3: argidx final
        far = s_argidx;
    }
    __syncthreads();
    for (int i = tid; i < S; i += 1024) {
        int f = fidx[b * S + i];
        float2 xy = sxy[f];
        float z = szp[f];
        sel_xyz[(b * S + i) * 3 + 0] = xy.x;
        sel_xyz[(b * S + i) * 3 + 1] = xy.y;
        sel_xyz[(b * S + i) * 3 + 2] = z;
        out_pc[b * 3 * S + 0 * S + i] = xy.x;
        out_pc[b * 3 * S + 1 * S + i] = xy.y;
        out_pc[b * 3 * S + 2 * S + i] = z;
        out_fidx[b * S + i] = (float)f;
    }
}

// ---------------- kNN (k=32), warp-per-query ----------------
// Block = 256 threads = 8 warps = 8 queries. Reference tiled through smem in
// CHUNK-point chunks shared by all 8 warps. Each lane keeps a sorted top-10 of
// its N/32 strided candidates (64-bit (dist-bits, idx) keys); then 32
// barrier-free warp-min extraction rounds.
template <int N, int S, int CHUNK>
__global__ void k_knn(const float* __restrict__ q, const float* __restrict__ ref,
                      int* __restrict__ nidx)
{
    constexpr int CAP = 10;
    __shared__ float sref[CHUNK * 3];
    const int tid  = threadIdx.x;
    const int lane = tid & 31;
    const int warp = tid >> 5;
    const int bq = blockIdx.x;
    const int b = bq / (S / 8);
    const int s = (bq % (S / 8)) * 8 + warp;

    const float qx = q[(b * S + s) * 3 + 0];
    const float qy = q[(b * S + s) * 3 + 1];
    const float qz = q[(b * S + s) * 3 + 2];
    const float qq = fmaf(qz, qz, fmaf(qy, qy, __fmul_rn(qx, qx)));

    unsigned long long k[CAP];
#pragma unroll
    for (int t = 0; t < CAP; t++) k[t] = ~0ull;

    const float* rb = ref + (size_t)b * N * 3;
    for (int ch = 0; ch < N; ch += CHUNK) {
        for (int i = tid; i < CHUNK * 3; i += 256) sref[i] = rb[ch * 3 + i];
        __syncthreads();
#pragma unroll 4
        for (int c = 0; c < CHUNK / 32; c++) {
            int il = c * 32 + lane;
            float rx = sref[il * 3 + 0];
            float ry = sref[il * 3 + 1];
            float rz = sref[il * 3 + 2];
            float dot = fmaf(qz, rz, fmaf(qy, ry, __fmul_rn(qx, rx)));
            float rr  = fmaf(rz, rz, fmaf(ry, ry, __fmul_rn(rx, rx)));
            float d = __fadd_rn(__fsub_rn(qq, __fmul_rn(2.f, dot)), rr);
            unsigned long long key = ((unsigned long long)fkey(d) << 32) | (unsigned)(ch + il);
            if (key < k[CAP - 1]) {
#pragma unroll
                for (int t = CAP - 1; t > 0; t--) k[t] = ullmax2(k[t - 1], ullmin2(k[t], key));
                k[0] = ullmin2(k[0], key);
            }
        }
        __syncthreads();
    }

    int* outp = nidx + ((size_t)(b * S + s)) * KK;
#pragma unroll 1
    for (int kk = 0; kk < KK; kk++) {
        unsigned long long m = k[0];
#pragma unroll
        for (int t = 1; t < CAP; t++) m = ullmin2(m, k[t]);
#pragma unroll
        for (int o = 16; o; o >>= 1) m = ullmin2(m, __shfl_xor_sync(0xffffffffu, m, o));
        if (lane == 0) outp[kk] = (int)(unsigned)(m & 0xffffffffu);
#pragma unroll
        for (int t = 0; t < CAP; t++) if (k[t] == m) k[t] = ~0ull;
    }
}

// ---------------- gather + first 1x1 conv + stats ----------------
template <int FDIM, int COUT, int SS, int NREF>
__global__ void k_gather_mm(const float* __restrict__ refxyz,
                            const float* __restrict__ reffeat,
                            const float* __restrict__ newxyz,
                            const int* __restrict__ nidx,
                            const float* __restrict__ W,
                            float* __restrict__ y,
                            float* __restrict__ sum, float* __restrict__ sq)
{
    constexpr int CIN = 3 + FDIM;
    __shared__ float sW[CIN * COUT];
    for (int i = threadIdx.x; i < CIN * COUT; i += blockDim.x) sW[i] = W[i];
    __syncthreads();

    int r = blockIdx.x * blockDim.x + threadIdx.x;
    int b = r / (SS * KK);
    int rem = r - b * (SS * KK);
    int s = rem / KK;
    int n = nidx[r];

    float in[CIN];
#pragma unroll
    for (int c = 0; c < 3; c++)
        in[c] = refxyz[((size_t)(b * NREF + n)) * 3 + c] - newxyz[((size_t)(b * SS + s)) * 3 + c];
#pragma unroll
    for (int j = 0; j < FDIM; j++)
        in[3 + j] = reffeat[((size_t)(b * NREF + n)) * FDIM + j];

    float acc[COUT];
#pragma unroll
    for (int c = 0; c < COUT; c++) acc[c] = 0.f;
#pragma unroll
    for (int j = 0; j < CIN; j++) {
        float v = in[j];
#pragma unroll
        for (int c = 0; c < COUT; c++) acc[c] = fmaf(v, sW[j * COUT + c], acc[c]);
    }
#pragma unroll
    for (int c = 0; c < COUT; c++)
        y[((size_t)(b * COUT + c)) * (SS * KK) + rem] = acc[c];

    int lane = threadIdx.x & 31;
#pragma unroll
    for (int c = 0; c < COUT; c++) {
        float v = acc[c], v2 = v * v;
#pragma unroll
        for (int o = 16; o; o >>= 1) {
            v  += __shfl_down_sync(0xffffffffu, v,  o);
            v2 += __shfl_down_sync(0xffffffffu, v2, o);
        }
        if (lane == 0) { atomicAdd(&sum[b * 64 + c], v); atomicAdd(&sq[b * 64 + c], v2); }
    }
}

// ---------------- instance-norm + relu + 1x1 conv + stats ----------------
template <int CIN, int COUT, int SS>
__global__ void k_mm(const float* __restrict__ x, const float* __restrict__ W,
                     const float* __restrict__ sumIn, const float* __restrict__ sqIn,
                     float* __restrict__ y,
                     float* __restrict__ sumOut, float* __restrict__ sqOut)
{
    __shared__ float sW[CIN * COUT];
    __shared__ float sMu[CIN], sInv[CIN];
    int r = blockIdx.x * blockDim.x + threadIdx.x;
    int b = r / (SS * KK);
    int rem = r - b * (SS * KK);
    for (int i = threadIdx.x; i < CIN * COUT; i += blockDim.x) sW[i] = W[i];
    if (threadIdx.x < CIN) {
        float cnt = (float)(SS * KK);
        float mu = sumIn[b * 64 + threadIdx.x] / cnt;
        float var = sqIn[b * 64 + threadIdx.x] / cnt - mu * mu;
        sMu[threadIdx.x] = mu;
        sInv[threadIdx.x] = rsqrtf(var + 1e-5f);
    }
    __syncthreads();

    float acc[COUT];
#pragma unroll
    for (int c = 0; c < COUT; c++) acc[c] = 0.f;
#pragma unroll
    for (int j = 0; j < CIN; j++) {
        float v = x[((size_t)(b * CIN + j)) * (SS * KK) + rem];
        v = fmaxf(0.f, (v - sMu[j]) * sInv[j]);
#pragma unroll
        for (int c = 0; c < COUT; c++) acc[c] = fmaf(v, sW[j * COUT + c], acc[c]);
    }
#pragma unroll
    for (int c = 0; c < COUT; c++)
        y[((size_t)(b * COUT + c)) * (SS * KK) + rem] = acc[c];

    int lane = threadIdx.x & 31;
#pragma unroll
    for (int c = 0; c < COUT; c++) {
        float v = acc[c], v2 = v * v;
#pragma unroll
        for (int o = 16; o; o >>= 1) {
            v  += __shfl_down_sync(0xffffffffu, v,  o);
            v2 += __shfl_down_sync(0xffffffffu, v2, o);
        }
        if (lane == 0) { atomicAdd(&sumOut[b * 64 + c], v); atomicAdd(&sqOut[b * 64 + c], v2); }
    }
}

// ---------------- instance-norm + relu + maxpool over K ----------------
template <int C, int SS, bool CHMAJOR>
__global__ void k_maxpool(const float* __restrict__ x,
                          const float* __restrict__ sumIn, const float* __restrict__ sqIn,
                          float* __restrict__ outp)
{
    int t = blockIdx.x * blockDim.x + threadIdx.x;   // over B*C*SS
    int s = t % SS;
    int c = (t / SS) % C;
    int b = t / (SS * C);
    float cnt = (float)(SS * KK);
    float mu = sumIn[b * 64 + c] / cnt;
    float var = sqIn[b * 64 + c] / cnt - mu * mu;
    float inv = rsqrtf(var + 1e-5f);

    const float4* p = reinterpret_cast<const float4*>(
        x + ((size_t)(b * C + c)) * (SS * KK) + (size_t)s * KK);
    float m = -3.4e38f;
#pragma unroll
    for (int qv = 0; qv < KK / 4; qv++) {
        float4 v = p[qv];
        m = fmaxf(m, fmaxf(fmaxf(v.x, v.y), fmaxf(v.z, v.w)));
    }
    // norm (inv>0) and relu are monotone: max(relu(norm(v))) == relu(norm(max v))
    float outv = fmaxf(0.f, (m - mu) * inv);
    if (CHMAJOR) outp[(b * C + c) * SS + s] = outv;
    else         outp[(b * SS + s) * C + c] = outv;
}

// ---------------- launch ----------------
extern "C" void kernel_launch(void* const* d_in, const int* in_sizes, int n_in,
                              void* d_out, int out_size)
{
    const float* pc     = (const float*)d_in[0];
    const float* feat   = (const float*)d_in[1];
    const float* sa1_w1 = (const float*)d_in[2];
    const float* sa1_w2 = (const float*)d_in[3];
    const float* sa1_w3 = (const float*)d_in[4];
    const float* sa2_w1 = (const float*)d_in[5];
    const float* sa2_w2 = (const float*)d_in[6];
    const float* sa2_w3 = (const float*)d_in[7];

    float* out = (float*)d_out;
    float* out_pc      = out;                       // 4*3*16384
    float* out_pc_l1   = out + 196608;              // 4*3*2048
    float* out_pc_l2   = out + 196608 + 24576;      // 4*3*1024
    float* out_feat_l2 = out + 196608 + 24576 + 12288;          // 4*64*1024
    float* out_fidx1   = out + 196608 + 24576 + 12288 + 262144; // 4*2048
    float* out_fidx2   = out + 196608 + 24576 + 12288 + 262144 + 8192; // 4*1024

    // device symbol addresses
    float *xyz0, *feat0, *xyz1, *xyz2, *feat1, *bufA, *bufB, *sum, *sq;
    int *fidx1, *fidx2, *nidx1, *nidx2;
    cudaGetSymbolAddress((void**)&xyz0,  g_xyz0);
    cudaGetSymbolAddress((void**)&feat0, g_feat0);
    cudaGetSymbolAddress((void**)&xyz1,  g_xyz1);
    cudaGetSymbolAddress((void**)&xyz2,  g_xyz2);
    cudaGetSymbolAddress((void**)&feat1, g_feat1);
    cudaGetSymbolAddress((void**)&bufA,  g_bufA);
    cudaGetSymbolAddress((void**)&bufB,  g_bufB);
    cudaGetSymbolAddress((void**)&sum,   g_sum);
    cudaGetSymbolAddress((void**)&sq,    g_sq);
    cudaGetSymbolAddress((void**)&fidx1, g_fidx1);
    cudaGetSymbolAddress((void**)&fidx2, g_fidx2);
    cudaGetSymbolAddress((void**)&nidx1, g_nidx1);
    cudaGetSymbolAddress((void**)&nidx2, g_nidx2);

    // opt-in shared memory for FPS stage 1 (192 KB)
    cudaFuncSetAttribute((const void*)k_fps<N0, S1V>,
                         cudaFuncAttributeMaxDynamicSharedMemorySize, 3 * N0 * 4);
    cudaFuncSetAttribute((const void*)k_fps<S1V, S2V>,
                         cudaFuncAttributeMaxDynamicSharedMemorySize, 3 * S1V * 4);

    k_zero<<<6, 256>>>();
    k_transpose<<<768, 256>>>(pc, feat, out_pc);

    // ---- stage 1 ----
    k_fps<N0, S1V><<<BB, 1024, 3 * N0 * 4>>>(xyz0, fidx1, xyz1, out_pc_l1, out_fidx1);
    k_knn<N0, S1V, 2048><<<BB * S1V / 8, 256>>>(xyz1, xyz0, nidx1);
    k_gather_mm<3, 32, S1V, N0><<<(BB * S1V * KK) / 256, 256>>>(
        xyz0, feat0, xyz1, nidx1, sa1_w1, bufA, sum + 0 * BB * 64, sq + 0 * BB * 64);
    k_mm<32, 32, S1V><<<(BB * S1V * KK) / 256, 256>>>(
        bufA, sa1_w2, sum + 0 * BB * 64, sq + 0 * BB * 64, bufB,
        sum + 1 * BB * 64, sq + 1 * BB * 64);
    k_mm<32, 32, S1V><<<(BB * S1V * KK) / 256, 256>>>(
        bufB, sa1_w3, sum + 1 * BB * 64, sq + 1 * BB * 64, bufA,
        sum + 2 * BB * 64, sq + 2 * BB * 64);
    k_maxpool<32, S1V, false><<<(BB * 32 * S1V) / 256, 256>>>(
        bufA, sum + 2 * BB * 64, sq + 2 * BB * 64, feat1);   // point-major [b][s][32]

    // ---- stage 2 ----
    k_fps<S1V, S2V><<<BB, 1024, 3 * S1V * 4>>>(xyz1, fidx2, xyz2, out_pc_l2, out_fidx2);
    k_knn<S1V, S2V, 2048><<<BB * S2V / 8, 256>>>(xyz2, xyz1, nidx2);
    k_gather_mm<32, 64, S2V, S1V><<<(BB * S2V * KK) / 256, 256>>>(
        xyz1, feat1, xyz2, nidx2, sa2_w1, bufA, sum + 3 * BB * 64, sq + 3 * BB * 64);
    k_mm<64, 64, S2V><<<(BB * S2V * KK) / 256, 256>>>(
        bufA, sa2_w2, sum + 3 * BB * 64, sq + 3 * BB * 64, bufB,
        sum + 4 * BB * 64, sq + 4 * BB * 64);
    k_mm<64, 64, S2V><<<(BB * S2V * KK) / 256, 256>>>(
        bufB, sa2_w3, sum + 4 * BB * 64, sq + 4 * BB * 64, bufA,
        sum + 5 * BB * 64, sq + 5 * BB * 64);
    k_maxpool<64, S2V, true><<<(BB * 64 * S2V) / 256, 256>>>(
        bufA, sum + 5 * BB * 64, sq + 5 * BB * 64, out_feat_l2); // channel-major
}

// round 6
// speedup vs baseline: 1.3202x; 1.1958x over previous
#include <cuda_runtime.h>
#include <cstdint>

#define BB  4
#define N0  16384
#define S1V 2048
#define S2V 1024
#define KK  32

// ---------------- device scratch (no allocations allowed) ----------------
__device__ __align__(16) float g_xyz0 [BB * N0  * 3];
__device__ __align__(16) float g_feat0[BB * N0  * 3];
__device__ __align__(16) float g_xyz1 [BB * S1V * 3];
__device__ __align__(16) float g_xyz2 [BB * S2V * 3];
__device__ int   g_fidx1[BB * S1V];
__device__ int   g_fidx2[BB * S2V];
__device__ int   g_nidx1[BB * S1V * KK];
__device__ int   g_nidx2[BB * S2V * KK];
__device__ __align__(16) float g_feat1[BB * S1V * 32];
__device__ __align__(16) float g_bufA [8388608];   // [b][c][s*K+k] channel-major
__device__ __align__(16) float g_bufB [8388608];
__device__ float g_sum[6 * BB * 64];
__device__ float g_sq [6 * BB * 64];

// ---------------- helpers ----------------
__device__ __forceinline__ unsigned fkey(float f) {
    unsigned u = __float_as_uint(f);
    return u ^ (((unsigned)((int)u >> 31)) | 0x80000000u);
}
__device__ __forceinline__ unsigned long long ullmin2(unsigned long long a, unsigned long long b){return a<b?a:b;}
__device__ __forceinline__ unsigned long long ullmax2(unsigned long long a, unsigned long long b){return a>b?a:b;}

// packed f32x2 ops (Blackwell). Per-lane rounding identical to scalar rn.
__device__ __forceinline__ unsigned long long pk2(float a, float b) {
    unsigned long long r; asm("mov.b64 %0, {%1, %2};" : "=l"(r) : "f"(a), "f"(b)); return r;
}
__device__ __forceinline__ void upk2(unsigned long long v, float& a, float& b) {
    asm("mov.b64 {%0, %1}, %2;" : "=f"(a), "=f"(b) : "l"(v));
}
__device__ __forceinline__ unsigned long long add2(unsigned long long a, unsigned long long b) {
    unsigned long long r; asm("add.rn.f32x2 %0, %1, %2;" : "=l"(r) : "l"(a), "l"(b)); return r;
}
__device__ __forceinline__ unsigned long long mul2(unsigned long long a, unsigned long long b) {
    unsigned long long r; asm("mul.rn.f32x2 %0, %1, %2;" : "=l"(r) : "l"(a), "l"(b)); return r;
}
__device__ __forceinline__ unsigned long long fma2(unsigned long long a, unsigned long long b, unsigned long long c) {
    unsigned long long r; asm("fma.rn.f32x2 %0, %1, %2, %3;" : "=l"(r) : "l"(a), "l"(b), "l"(c)); return r;
}

// ---------------- zero stats ----------------
__global__ void k_zero() {
    int t = blockIdx.x * blockDim.x + threadIdx.x;
    if (t < 6 * BB * 64) { g_sum[t] = 0.f; g_sq[t] = 0.f; }
}

// ---------------- transpose [B,3,N] -> [B,N,3] + copy pc to out ----------------
__global__ void k_transpose(const float* __restrict__ pc, const float* __restrict__ feat,
                            float* __restrict__ out_pc) {
    int i = blockIdx.x * blockDim.x + threadIdx.x;
    if (i < BB * 3 * N0) {
        int b = i / (3 * N0);
        int c = (i / N0) % 3;
        int n = i % N0;
        float v = pc[i];
        g_xyz0 [(b * N0 + n) * 3 + c] = v;
        g_feat0[(b * N0 + n) * 3 + c] = feat[i];
        out_pc[i] = v;
    }
}

// ---------------- farthest point sampling ----------------
// LOAD-BEARING for bit-compat with the XLA reference (do not alter):
//   * distance form rn(fma(dz,dz, fma(dy,dy, rn(dx*dx)))) with dx = rn(x + (-cx))
//   * exact block max, then 1-ulp tie window with minimum-index selection
// x/y live in registers packed 2-points-per-f32x2; z streamed from smem.
template <int N, int S, int T>
__global__ void __launch_bounds__(T, 1)
k_fps(const float* __restrict__ xyz, int* __restrict__ fidx,
      float* __restrict__ sel_xyz,   // [b][s][3]
      float* __restrict__ out_pc,    // [b][3][S]
      float* __restrict__ out_fidx)  // [b][S] as float
{
    extern __shared__ float sm[];
    float2* sxy = (float2*)sm;        // N x (x,y)  (centroid lookup + output only)
    float*  szp = sm + 2 * N;         // N x z
    __shared__ unsigned s_maxbits;
    __shared__ int      s_argidx;
    __shared__ float    s_ncx, s_ncy, s_ncz;   // negated centroid

    const int tid = threadIdx.x;
    const int b = blockIdx.x;
    const float* base = xyz + (size_t)b * N * 3;
    constexpr int P = N / T;          // points per thread
    constexpr int PAIRS = P / 2;      // pair j: p0 = tid + j*2T, p1 = p0 + T

    unsigned long long X[PAIRS], Y[PAIRS];
    float dist[P];
#pragma unroll
    for (int j = 0; j < PAIRS; j++) {
        int p0 = tid + j * (2 * T);
        int p1 = p0 + T;
        float x0 = base[p0 * 3 + 0], y0 = base[p0 * 3 + 1], z0 = base[p0 * 3 + 2];
        float x1 = base[p1 * 3 + 0], y1 = base[p1 * 3 + 1], z1 = base[p1 * 3 + 2];
        sxy[p0] = make_float2(x0, y0);  szp[p0] = z0;
        sxy[p1] = make_float2(x1, y1);  szp[p1] = z1;
        X[j] = pk2(x0, x1);
        Y[j] = pk2(y0, y1);
        dist[2 * j] = 1e10f; dist[2 * j + 1] = 1e10f;
    }
    __syncthreads();

    int far = 0;
    for (int i = 0; i < S; i++) {
        if (tid == 0) {
            fidx[b * S + i] = far;
            float2 c = sxy[far];
            s_ncx = -c.x; s_ncy = -c.y; s_ncz = -szp[far];
            s_maxbits = 0u;
            s_argidx  = 0x7fffffff;
        }
        __syncthreads();                               // 1: centroid + resets visible
        const unsigned long long ncx2 = pk2(s_ncx, s_ncx);
        const unsigned long long ncy2 = pk2(s_ncy, s_ncy);
        const unsigned long long ncz2 = pk2(s_ncz, s_ncz);
        float mval = 0.f;
#pragma unroll
        for (int j = 0; j < PAIRS; j++) {
            int p0 = tid + j * (2 * T);
            unsigned long long dx = add2(X[j], ncx2);              // rn(x - cx) per lane
            unsigned long long dy = add2(Y[j], ncy2);
            unsigned long long zz = pk2(szp[p0], szp[p0 + T]);
            unsigned long long dz = add2(zz, ncz2);
            unsigned long long t  = mul2(dx, dx);                  // rn(dx*dx)
            t = fma2(dy, dy, t);                                   // fused, per lane
            t = fma2(dz, dz, t);
            float da, db; upk2(t, da, db);
            float n0 = fminf(dist[2 * j],     da);
            float n1 = fminf(dist[2 * j + 1], db);
            dist[2 * j]     = n0;
            dist[2 * j + 1] = n1;
            mval = fmaxf(mval, fmaxf(n0, n1));
        }
        float wmax = mval;
#pragma unroll
        for (int o = 16; o; o >>= 1) wmax = fmaxf(wmax, __shfl_xor_sync(0xffffffffu, wmax, o));
        if ((tid & 31) == 0) atomicMax(&s_maxbits, __float_as_uint(wmax));
        __syncthreads();                               // 2: global max final
        const unsigned gbits = s_maxbits;
        if (gbits - __float_as_uint(mval) <= 1u) {     // only candidate threads rescan
#pragma unroll
            for (int j = 0; j < P; j++) {
                // dist >= 0 -> bits monotone; accept exact max and 1 ulp below
                if (gbits - __float_as_uint(dist[j]) <= 1u) {
                    int p = tid + (j >> 1) * (2 * T) + (j & 1) * T;
                    atomicMin(&s_argidx, p);
                }
            }
        }
        __syncthreads();                               // 3: argidx final
        far = s_argidx;
    }
    __syncthreads();
    for (int i = tid; i < S; i += T) {
        int f = fidx[b * S + i];
        float2 xy = sxy[f];
        float z = szp[f];
        sel_xyz[(b * S + i) * 3 + 0] = xy.x;
        sel_xyz[(b * S + i) * 3 + 1] = xy.y;
        sel_xyz[(b * S + i) * 3 + 2] = z;
        out_pc[b * 3 * S + 0 * S + i] = xy.x;
        out_pc[b * 3 * S + 1 * S + i] = xy.y;
        out_pc[b * 3 * S + 2 * S + i] = z;
        out_fidx[b * S + i] = (float)f;
    }
}

// ---------------- kNN (k=32), warp-per-query ----------------
// Block = 256 threads = 8 warps = 8 queries; reference tiled through smem.
// Per-lane sorted top-10 with a cached 32-bit distance threshold so the common
// path is one compare; 32 barrier-free warp-min extraction rounds.
template <int N, int S, int CHUNK>
__global__ void k_knn(const float* __restrict__ q, const float* __restrict__ ref,
                      int* __restrict__ nidx)
{
    constexpr int CAP = 10;
    __shared__ float sref[CHUNK * 3];
    const int tid  = threadIdx.x;
    const int lane = tid & 31;
    const int warp = tid >> 5;
    const int bq = blockIdx.x;
    const int b = bq / (S / 8);
    const int s = (bq % (S / 8)) * 8 + warp;

    const float qx = q[(b * S + s) * 3 + 0];
    const float qy = q[(b * S + s) * 3 + 1];
    const float qz = q[(b * S + s) * 3 + 2];
    const float qq = fmaf(qz, qz, fmaf(qy, qy, __fmul_rn(qx, qx)));

    unsigned long long k[CAP];
#pragma unroll
    for (int t = 0; t < CAP; t++) k[t] = ~0ull;
    unsigned thr = 0xffffffffu;   // high word of k[CAP-1]

    const float* rb = ref + (size_t)b * N * 3;
    for (int ch = 0; ch < N; ch += CHUNK) {
        for (int i = tid; i < CHUNK * 3; i += 256) sref[i] = rb[ch * 3 + i];
        __syncthreads();
#pragma unroll 4
        for (int c = 0; c < CHUNK / 32; c++) {
            int il = c * 32 + lane;
            float rx = sref[il * 3 + 0];
            float ry = sref[il * 3 + 1];
            float rz = sref[il * 3 + 2];
            float dot = fmaf(qz, rz, fmaf(qy, ry, __fmul_rn(qx, rx)));
            float rr  = fmaf(rz, rz, fmaf(ry, ry, __fmul_rn(rx, rx)));
            float d = __fadd_rn(__fsub_rn(qq, __fmul_rn(2.f, dot)), rr);
            unsigned dk = fkey(d);
            if (dk <= thr) {   // cheap filter; equality case harmlessly inserts
                unsigned long long key = ((unsigned long long)dk << 32) | (unsigned)(ch + il);
                if (key < k[CAP - 1]) {
#pragma unroll
                    for (int t = CAP - 1; t > 0; t--) k[t] = ullmax2(k[t - 1], ullmin2(k[t], key));
                    k[0] = ullmin2(k[0], key);
                    thr = (unsigned)(k[CAP - 1] >> 32);
                }
            }
        }
        __syncthreads();
    }

    int* outp = nidx + ((size_t)(b * S + s)) * KK;
#pragma unroll 1
    for (int kk = 0; kk < KK; kk++) {
        unsigned long long m = k[0];
#pragma unroll
        for (int t = 1; t < CAP; t++) m = ullmin2(m, k[t]);
#pragma unroll
        for (int o = 16; o; o >>= 1) m = ullmin2(m, __shfl_xor_sync(0xffffffffu, m, o));
        if (lane == 0) outp[kk] = (int)(unsigned)(m & 0xffffffffu);
#pragma unroll
        for (int t = 0; t < CAP; t++) if (k[t] == m) k[t] = ~0ull;
    }
}

// ---------------- gather + first 1x1 conv + stats ----------------
template <int FDIM, int COUT, int SS, int NREF>
__global__ void k_gather_mm(const float* __restrict__ refxyz,
                            const float* __restrict__ reffeat,
                            const float* __restrict__ newxyz,
                            const int* __restrict__ nidx,
                            const float* __restrict__ W,
                            float* __restrict__ y,
                            float* __restrict__ sum, float* __restrict__ sq)
{
    constexpr int CIN = 3 + FDIM;
    __shared__ float sW[CIN * COUT];
    for (int i = threadIdx.x; i < CIN * COUT; i += blockDim.x) sW[i] = W[i];
    __syncthreads();

    int r = blockIdx.x * blockDim.x + threadIdx.x;
    int b = r / (SS * KK);
    int rem = r - b * (SS * KK);
    int s = rem / KK;
    int n = nidx[r];

    float in[CIN];
#pragma unroll
    for (int c = 0; c < 3; c++)
        in[c] = refxyz[((size_t)(b * NREF + n)) * 3 + c] - newxyz[((size_t)(b * SS + s)) * 3 + c];
#pragma unroll
    for (int j = 0; j < FDIM; j++)
        in[3 + j] = reffeat[((size_t)(b * NREF + n)) * FDIM + j];

    float acc[COUT];
#pragma unroll
    for (int c = 0; c < COUT; c++) acc[c] = 0.f;
#pragma unroll
    for (int j = 0; j < CIN; j++) {
        float v = in[j];
#pragma unroll
        for (int c = 0; c < COUT; c++) acc[c] = fmaf(v, sW[j * COUT + c], acc[c]);
    }
#pragma unroll
    for (int c = 0; c < COUT; c++)
        y[((size_t)(b * COUT + c)) * (SS * KK) + rem] = acc[c];

    int lane = threadIdx.x & 31;
#pragma unroll
    for (int c = 0; c < COUT; c++) {
        float v = acc[c], v2 = v * v;
#pragma unroll
        for (int o = 16; o; o >>= 1) {
            v  += __shfl_down_sync(0xffffffffu, v,  o);
            v2 += __shfl_down_sync(0xffffffffu, v2, o);
        }
        if (lane == 0) { atomicAdd(&sum[b * 64 + c], v); atomicAdd(&sq[b * 64 + c], v2); }
    }
}

// ---------------- instance-norm + relu + 1x1 conv + stats ----------------
template <int CIN, int COUT, int SS>
__global__ void k_mm(const float* __restrict__ x, const float* __restrict__ W,
                     const float* __restrict__ sumIn, const float* __restrict__ sqIn,
                     float* __restrict__ y,
                     float* __restrict__ sumOut, float* __restrict__ sqOut)
{
    __shared__ float sW[CIN * COUT];
    __shared__ float sMu[CIN], sInv[CIN];
    int r = blockIdx.x * blockDim.x + threadIdx.x;
    int b = r / (SS * KK);
    int rem = r - b * (SS * KK);
    for (int i = threadIdx.x; i < CIN * COUT; i += blockDim.x) sW[i] = W[i];
    if (threadIdx.x < CIN) {
        float cnt = (float)(SS * KK);
        float mu = sumIn[b * 64 + threadIdx.x] / cnt;
        float var = sqIn[b * 64 + threadIdx.x] / cnt - mu * mu;
        sMu[threadIdx.x] = mu;
        sInv[threadIdx.x] = rsqrtf(var + 1e-5f);
    }
    __syncthreads();

    float acc[COUT];
#pragma unroll
    for (int c = 0; c < COUT; c++) acc[c] = 0.f;
#pragma unroll
    for (int j = 0; j < CIN; j++) {
        float v = x[((size_t)(b * CIN + j)) * (SS * KK) + rem];
        v = fmaxf(0.f, (v - sMu[j]) * sInv[j]);
#pragma unroll
        for (int c = 0; c < COUT; c++) acc[c] = fmaf(v, sW[j * COUT + c], acc[c]);
    }
#pragma unroll
    for (int c = 0; c < COUT; c++)
        y[((size_t)(b * COUT + c)) * (SS * KK) + rem] = acc[c];

    int lane = threadIdx.x & 31;
#pragma unroll
    for (int c = 0; c < COUT; c++) {
        float v = acc[c], v2 = v * v;
#pragma unroll
        for (int o = 16; o; o >>= 1) {
            v  += __shfl_down_sync(0xffffffffu, v,  o);
            v2 += __shfl_down_sync(0xffffffffu, v2, o);
        }
        if (lane == 0) { atomicAdd(&sumOut[b * 64 + c], v); atomicAdd(&sqOut[b * 64 + c], v2); }
    }
}

// ---------------- instance-norm + relu + maxpool over K ----------------
template <int C, int SS, bool CHMAJOR>
__global__ void k_maxpool(const float* __restrict__ x,
                          const float* __restrict__ sumIn, const float* __restrict__ sqIn,
                          float* __restrict__ outp)
{
    int t = blockIdx.x * blockDim.x + threadIdx.x;   // over B*C*SS
    int s = t % SS;
    int c = (t / SS) % C;
    int b = t / (SS * C);
    float cnt = (float)(SS * KK);
    float mu = sumIn[b * 64 + c] / cnt;
    float var = sqIn[b * 64 + c] / cnt - mu * mu;
    float inv = rsqrtf(var + 1e-5f);

    const float4* p = reinterpret_cast<const float4*>(
        x + ((size_t)(b * C + c)) * (SS * KK) + (size_t)s * KK);
    float m = -3.4e38f;
#pragma unroll
    for (int qv = 0; qv < KK / 4; qv++) {
        float4 v = p[qv];
        m = fmaxf(m, fmaxf(fmaxf(v.x, v.y), fmaxf(v.z, v.w)));
    }
    // norm (inv>0) and relu are monotone: max(relu(norm(v))) == relu(norm(max v))
    float outv = fmaxf(0.f, (m - mu) * inv);
    if (CHMAJOR) outp[(b * C + c) * SS + s] = outv;
    else         outp[(b * SS + s) * C + c] = outv;
}

// ---------------- launch ----------------
extern "C" void kernel_launch(void* const* d_in, const int* in_sizes, int n_in,
                              void* d_out, int out_size)
{
    const float* pc     = (const float*)d_in[0];
    const float* feat   = (const float*)d_in[1];
    const float* sa1_w1 = (const float*)d_in[2];
    const float* sa1_w2 = (const float*)d_in[3];
    const float* sa1_w3 = (const float*)d_in[4];
    const float* sa2_w1 = (const float*)d_in[5];
    const float* sa2_w2 = (const float*)d_in[6];
    const float* sa2_w3 = (const float*)d_in[7];

    float* out = (float*)d_out;
    float* out_pc      = out;                       // 4*3*16384
    float* out_pc_l1   = out + 196608;              // 4*3*2048
    float* out_pc_l2   = out + 196608 + 24576;      // 4*3*1024
    float* out_feat_l2 = out + 196608 + 24576 + 12288;          // 4*64*1024
    float* out_fidx1   = out + 196608 + 24576 + 12288 + 262144; // 4*2048
    float* out_fidx2   = out + 196608 + 24576 + 12288 + 262144 + 8192; // 4*1024

    // device symbol addresses
    float *xyz0, *feat0, *xyz1, *xyz2, *feat1, *bufA, *bufB, *sum, *sq;
    int *fidx1, *fidx2, *nidx1, *nidx2;
    cudaGetSymbolAddress((void**)&xyz0,  g_xyz0);
    cudaGetSymbolAddress((void**)&feat0, g_feat0);
    cudaGetSymbolAddress((void**)&xyz1,  g_xyz1);
    cudaGetSymbolAddress((void**)&xyz2,  g_xyz2);
    cudaGetSymbolAddress((void**)&feat1, g_feat1);
    cudaGetSymbolAddress((void**)&bufA,  g_bufA);
    cudaGetSymbolAddress((void**)&bufB,  g_bufB);
    cudaGetSymbolAddress((void**)&sum,   g_sum);
    cudaGetSymbolAddress((void**)&sq,    g_sq);
    cudaGetSymbolAddress((void**)&fidx1, g_fidx1);
    cudaGetSymbolAddress((void**)&fidx2, g_fidx2);
    cudaGetSymbolAddress((void**)&nidx1, g_nidx1);
    cudaGetSymbolAddress((void**)&nidx2, g_nidx2);

    // opt-in shared memory for FPS (192 KB stage 1)
    cudaFuncSetAttribute((const void*)k_fps<N0, S1V, 512>,
                         cudaFuncAttributeMaxDynamicSharedMemorySize, 3 * N0 * 4);
    cudaFuncSetAttribute((const void*)k_fps<S1V, S2V, 512>,
                         cudaFuncAttributeMaxDynamicSharedMemorySize, 3 * S1V * 4);

    k_zero<<<6, 256>>>();
    k_transpose<<<768, 256>>>(pc, feat, out_pc);

    // ---- stage 1 ----
    k_fps<N0, S1V, 512><<<BB, 512, 3 * N0 * 4>>>(xyz0, fidx1, xyz1, out_pc_l1, out_fidx1);
    k_knn<N0, S1V, 2048><<<BB * S1V / 8, 256>>>(xyz1, xyz0, nidx1);
    k_gather_mm<3, 32, S1V, N0><<<(BB * S1V * KK) / 256, 256>>>(
        xyz0, feat0, xyz1, nidx1, sa1_w1, bufA, sum + 0 * BB * 64, sq + 0 * BB * 64);
    k_mm<32, 32, S1V><<<(BB * S1V * KK) / 256, 256>>>(
        bufA, sa1_w2, sum + 0 * BB * 64, sq + 0 * BB * 64, bufB,
        sum + 1 * BB * 64, sq + 1 * BB * 64);
    k_mm<32, 32, S1V><<<(BB * S1V * KK) / 256, 256>>>(
        bufB, sa1_w3, sum + 1 * BB * 64, sq + 1 * BB * 64, bufA,
        sum + 2 * BB * 64, sq + 2 * BB * 64);
    k_maxpool<32, S1V, false><<<(BB * 32 * S1V) / 256, 256>>>(
        bufA, sum + 2 * BB * 64, sq + 2 * BB * 64, feat1);   // point-major [b][s][32]

    // ---- stage 2 ----
    k_fps<S1V, S2V, 512><<<BB, 512, 3 * S1V * 4>>>(xyz1, fidx2, xyz2, out_pc_l2, out_fidx2);
    k_knn<S1V, S2V, 2048><<<BB * S2V / 8, 256>>>(xyz2, xyz1, nidx2);
    k_gather_mm<32, 64, S2V, S1V><<<(BB * S2V * KK) / 256, 256>>>(
        xyz1, feat1, xyz2, nidx2, sa2_w1, bufA, sum + 3 * BB * 64, sq + 3 * BB * 64);
    k_mm<64, 64, S2V><<<(BB * S2V * KK) / 256, 256>>>(
        bufA, sa2_w2, sum + 3 * BB * 64, sq + 3 * BB * 64, bufB,
        sum + 4 * BB * 64, sq + 4 * BB * 64);
    k_mm<64, 64, S2V><<<(BB * S2V * KK) / 256, 256>>>(
        bufB, sa2_w3, sum + 4 * BB * 64, sq + 4 * BB * 64, bufA,
        sum + 5 * BB * 64, sq + 5 * BB * 64);
    k_maxpool<64, S2V, true><<<(BB * 64 * S2V) / 256, 256>>>(
        bufA, sum + 5 * BB * 64, sq + 5 * BB * 64, out_feat_l2); // channel-major
}

// round 7
// speedup vs baseline: 1.5541x; 1.1772x over previous
#include <cuda_runtime.h>
#include <cstdint>

#define BB  4
#define N0  16384
#define S1V 2048
#define S2V 1024
#define KK  32

// ---------------- device scratch (no allocations allowed) ----------------
__device__ __align__(16) float g_xyz0 [BB * N0  * 3];
__device__ __align__(16) float g_feat0[BB * N0  * 3];
__device__ __align__(16) float g_xyz1 [BB * S1V * 3];
__device__ __align__(16) float g_xyz2 [BB * S2V * 3];
__device__ int   g_fidx1[BB * S1V];
__device__ int   g_fidx2[BB * S2V];
__device__ int   g_nidx1[BB * S1V * KK];
__device__ int   g_nidx2[BB * S2V * KK];
__device__ __align__(16) float g_feat1[BB * S1V * 32];
__device__ __align__(16) float g_bufA [8388608];   // [b][c][s*K+k] channel-major
__device__ __align__(16) float g_bufB [8388608];
__device__ float g_sum[6 * BB * 64];
__device__ float g_sq [6 * BB * 64];
__device__ __align__(16) float g_dist[BB * N0];    // FPS segment-persisted min-dist
__device__ int   g_far[BB];

// ---------------- helpers ----------------
__device__ __forceinline__ unsigned fkey(float f) {
    unsigned u = __float_as_uint(f);
    return u ^ (((unsigned)((int)u >> 31)) | 0x80000000u);
}
__device__ __forceinline__ unsigned long long ullmin2(unsigned long long a, unsigned long long b){return a<b?a:b;}
__device__ __forceinline__ unsigned long long ullmax2(unsigned long long a, unsigned long long b){return a>b?a:b;}

// packed f32x2 ops (Blackwell). Per-lane rounding identical to scalar rn.
__device__ __forceinline__ unsigned long long pk2(float a, float b) {
    unsigned long long r; asm("mov.b64 %0, {%1, %2};" : "=l"(r) : "f"(a), "f"(b)); return r;
}
__device__ __forceinline__ void upk2(unsigned long long v, float& a, float& b) {
    asm("mov.b64 {%0, %1}, %2;" : "=f"(a), "=f"(b) : "l"(v));
}
__device__ __forceinline__ unsigned long long add2(unsigned long long a, unsigned long long b) {
    unsigned long long r; asm("add.rn.f32x2 %0, %1, %2;" : "=l"(r) : "l"(a), "l"(b)); return r;
}
__device__ __forceinline__ unsigned long long mul2(unsigned long long a, unsigned long long b) {
    unsigned long long r; asm("mul.rn.f32x2 %0, %1, %2;" : "=l"(r) : "l"(a), "l"(b)); return r;
}
__device__ __forceinline__ unsigned long long fma2(unsigned long long a, unsigned long long b, unsigned long long c) {
    unsigned long long r; asm("fma.rn.f32x2 %0, %1, %2, %3;" : "=l"(r) : "l"(a), "l"(b), "l"(c)); return r;
}

// ---------------- zero stats ----------------
__global__ void k_zero() {
    int t = blockIdx.x * blockDim.x + threadIdx.x;
    if (t < 6 * BB * 64) { g_sum[t] = 0.f; g_sq[t] = 0.f; }
}

// ---------------- transpose [B,3,N] -> [B,N,3] + copy pc to out ----------------
__global__ void k_transpose(const float* __restrict__ pc, const float* __restrict__ feat,
                            float* __restrict__ out_pc) {
    int i = blockIdx.x * blockDim.x + threadIdx.x;
    if (i < BB * 3 * N0) {
        int b = i / (3 * N0);
        int c = (i / N0) % 3;
        int n = i % N0;
        float v = pc[i];
        g_xyz0 [(b * N0 + n) * 3 + c] = v;
        g_feat0[(b * N0 + n) * 3 + c] = feat[i];
        out_pc[i] = v;
    }
}

// ---------------- farthest point sampling (segmented) ----------------
// LOAD-BEARING for bit-compat with the XLA reference (do not alter):
//   * distance form rn(fma(dz,dz, fma(dy,dy, rn(dx*dx)))) with dx = rn(x + (-cx))
//   * exact block max, then 1-ulp tie window with minimum-index selection
// fminf is exact+associative, so segmenting with dist persisted to global is
// bit-identical to one pass. Outputs for iteration i are written by tid0 at i.
template <int N, int S, int T>
__global__ void __launch_bounds__(T, 1)
k_fps(const float* __restrict__ xyz, int* __restrict__ fidx,
      float* __restrict__ sel_xyz,   // [b][s][3]
      float* __restrict__ out_pc,    // [b][3][S]
      float* __restrict__ out_fidx,  // [b][S] as float
      int i0, int i1)
{
    extern __shared__ float sm[];
    float2* sxy = (float2*)sm;        // N x (x,y)
    float*  szp = sm + 2 * N;         // N x z
    __shared__ unsigned s_maxbits;
    __shared__ int      s_argidx;
    __shared__ float    s_ncx, s_ncy, s_ncz;   // negated centroid

    const int tid = threadIdx.x;
    const int b = blockIdx.x;
    const float* base = xyz + (size_t)b * N * 3;
    constexpr int P = N / T;
    constexpr int PAIRS = P / 2;      // pair j: p0 = tid + j*2T, p1 = p0 + T

    unsigned long long X[PAIRS], Y[PAIRS];
    float dist[P];
#pragma unroll
    for (int j = 0; j < PAIRS; j++) {
        int p0 = tid + j * (2 * T);
        int p1 = p0 + T;
        float x0 = base[p0 * 3 + 0], y0 = base[p0 * 3 + 1], z0 = base[p0 * 3 + 2];
        float x1 = base[p1 * 3 + 0], y1 = base[p1 * 3 + 1], z1 = base[p1 * 3 + 2];
        sxy[p0] = make_float2(x0, y0);  szp[p0] = z0;
        sxy[p1] = make_float2(x1, y1);  szp[p1] = z1;
        X[j] = pk2(x0, x1);
        Y[j] = pk2(y0, y1);
        if (i0 == 0) { dist[2 * j] = 1e10f; dist[2 * j + 1] = 1e10f; }
        else { dist[2 * j] = g_dist[b * N + p0]; dist[2 * j + 1] = g_dist[b * N + p1]; }
    }
    int far = (i0 == 0) ? 0 : g_far[b];
    __syncthreads();

    for (int i = i0; i < i1; i++) {
        if (tid == 0) {
            float2 c = sxy[far];
            float cz = szp[far];
            fidx[b * S + i] = far;
            sel_xyz[(b * S + i) * 3 + 0] = c.x;
            sel_xyz[(b * S + i) * 3 + 1] = c.y;
            sel_xyz[(b * S + i) * 3 + 2] = cz;
            out_pc[b * 3 * S + 0 * S + i] = c.x;
            out_pc[b * 3 * S + 1 * S + i] = c.y;
            out_pc[b * 3 * S + 2 * S + i] = cz;
            out_fidx[b * S + i] = (float)far;
            s_ncx = -c.x; s_ncy = -c.y; s_ncz = -cz;
            s_maxbits = 0u;
            s_argidx  = 0x7fffffff;
        }
        __syncthreads();                               // 1
        const unsigned long long ncx2 = pk2(s_ncx, s_ncx);
        const unsigned long long ncy2 = pk2(s_ncy, s_ncy);
        const unsigned long long ncz2 = pk2(s_ncz, s_ncz);
        float mval = 0.f;
#pragma unroll
        for (int j = 0; j < PAIRS; j++) {
            int p0 = tid + j * (2 * T);
            unsigned long long dx = add2(X[j], ncx2);
            unsigned long long dy = add2(Y[j], ncy2);
            unsigned long long zz = pk2(szp[p0], szp[p0 + T]);
            unsigned long long dz = add2(zz, ncz2);
            unsigned long long t  = mul2(dx, dx);
            t = fma2(dy, dy, t);
            t = fma2(dz, dz, t);
            float da, db; upk2(t, da, db);
            float n0 = fminf(dist[2 * j],     da);
            float n1 = fminf(dist[2 * j + 1], db);
            dist[2 * j]     = n0;
            dist[2 * j + 1] = n1;
            mval = fmaxf(mval, fmaxf(n0, n1));
        }
        float wmax = mval;
#pragma unroll
        for (int o = 16; o; o >>= 1) wmax = fmaxf(wmax, __shfl_xor_sync(0xffffffffu, wmax, o));
        if ((tid & 31) == 0) atomicMax(&s_maxbits, __float_as_uint(wmax));
        __syncthreads();                               // 2
        const unsigned gbits = s_maxbits;
        if (gbits - __float_as_uint(mval) <= 1u) {
#pragma unroll
            for (int j = 0; j < P; j++) {
                if (gbits - __float_as_uint(dist[j]) <= 1u) {
                    int p = tid + (j >> 1) * (2 * T) + (j & 1) * T;
                    atomicMin(&s_argidx, p);
                }
            }
        }
        __syncthreads();                               // 3
        far = s_argidx;
    }

    if (i1 < S) {   // persist segment state
#pragma unroll
        for (int j = 0; j < P; j++) {
            int p = tid + (j >> 1) * (2 * T) + (j & 1) * T;
            g_dist[b * N + p] = dist[j];
        }
        if (tid == 0) g_far[b] = far;
    }
}

// ---------------- kNN (k=32): warp-cooperative exact bitonic top-32 ----------------
// Warp per query; the warp holds the running top-32 distributed one key per
// lane, sorted ascending (lane 0 = nearest). Per 32-candidate batch: ballot
// skip vs lane-31 threshold, else bitonic-sort batch + min-merge + re-sort.
__device__ __forceinline__ unsigned long long bitonic_sort32(unsigned long long v, int lane) {
#pragma unroll
    for (int k = 2; k <= 32; k <<= 1) {
#pragma unroll
        for (int j = k >> 1; j; j >>= 1) {
            unsigned long long o = __shfl_xor_sync(0xffffffffu, v, j);
            bool up    = (lane & k) == 0;
            bool lower = (lane & j) == 0;
            v = (lower == up) ? ullmin2(v, o) : ullmax2(v, o);
        }
    }
    return v;
}
__device__ __forceinline__ unsigned long long bitonic_merge32(unsigned long long v, int lane) {
#pragma unroll
    for (int j = 16; j; j >>= 1) {
        unsigned long long o = __shfl_xor_sync(0xffffffffu, v, j);
        v = ((lane & j) == 0) ? ullmin2(v, o) : ullmax2(v, o);
    }
    return v;
}

template <int N, int S, int CHUNK>
__global__ void k_knn(const float* __restrict__ q, const float* __restrict__ ref,
                      int* __restrict__ nidx, int q0, int nq)
{
    __shared__ float sref[CHUNK * 3];
    const int tid  = threadIdx.x;
    const int lane = tid & 31;
    const int warp = tid >> 5;
    const int per_b = nq / 8;
    const int b = blockIdx.x / per_b;
    const int s = q0 + (blockIdx.x % per_b) * 8 + warp;

    const float qx = q[(b * S + s) * 3 + 0];
    const float qy = q[(b * S + s) * 3 + 1];
    const float qz = q[(b * S + s) * 3 + 2];
    const float qq = fmaf(qz, qz, fmaf(qy, qy, __fmul_rn(qx, qx)));

    unsigned long long topv = ~0ull;          // lane's element of warp top-32
    unsigned long long thr  = ~0ull;          // lane-31 value (current 32nd best)

    const float* rb = ref + (size_t)b * N * 3;
    for (int ch = 0; ch < N; ch += CHUNK) {
        for (int i = tid; i < CHUNK * 3; i += 256) sref[i] = rb[ch * 3 + i];
        __syncthreads();
#pragma unroll 2
        for (int c = 0; c < CHUNK / 32; c++) {
            int il = c * 32 + lane;
            float rx = sref[il * 3 + 0];
            float ry = sref[il * 3 + 1];
            float rz = sref[il * 3 + 2];
            float dot = fmaf(qz, rz, fmaf(qy, ry, __fmul_rn(qx, rx)));
            float rr  = fmaf(rz, rz, fmaf(ry, ry, __fmul_rn(rx, rx)));
            float d = __fadd_rn(__fsub_rn(qq, __fmul_rn(2.f, dot)), rr);
            unsigned long long key = ((unsigned long long)fkey(d) << 32) | (unsigned)(ch + il);
            if (__ballot_sync(0xffffffffu, key < thr)) {
                unsigned long long v = bitonic_sort32(key, lane);       // batch ascending
                unsigned long long w = __shfl_xor_sync(0xffffffffu, v, 31); // reversed
                topv = bitonic_merge32(ullmin2(topv, w), lane);
                thr = __shfl_sync(0xffffffffu, topv, 31);
            }
        }
        __syncthreads();
    }
    // lane k holds the k-th nearest (ascending d, ties by lower index)
    nidx[((size_t)(b * S + s)) * KK + lane] = (int)(unsigned)(topv & 0xffffffffu);
}

// ---------------- gather + first 1x1 conv + stats (chunkable over s) ----------------
template <int FDIM, int COUT, int SS, int NREF>
__global__ void k_gather_mm(const float* __restrict__ refxyz,
                            const float* __restrict__ reffeat,
                            const float* __restrict__ newxyz,
                            const int* __restrict__ nidx,
                            const float* __restrict__ W,
                            float* __restrict__ y,
                            float* __restrict__ sum, float* __restrict__ sq,
                            int q0, int nq)
{
    constexpr int CIN = 3 + FDIM;
    __shared__ float sW[CIN * COUT];
    for (int i = threadIdx.x; i < CIN * COUT; i += blockDim.x) sW[i] = W[i];
    __syncthreads();

    int r0 = blockIdx.x * blockDim.x + threadIdx.x;
    int per_b = nq * KK;
    int b = r0 / per_b;
    int rem = q0 * KK + (r0 - b * per_b);
    int s = rem / KK;
    int n = nidx[(size_t)b * (SS * KK) + rem];

    float in[CIN];
#pragma unroll
    for (int c = 0; c < 3; c++)
        in[c] = refxyz[((size_t)(b * NREF + n)) * 3 + c] - newxyz[((size_t)(b * SS + s)) * 3 + c];
#pragma unroll
    for (int j = 0; j < FDIM; j++)
        in[3 + j] = reffeat[((size_t)(b * NREF + n)) * FDIM + j];

    float acc[COUT];
#pragma unroll
    for (int c = 0; c < COUT; c++) acc[c] = 0.f;
#pragma unroll
    for (int j = 0; j < CIN; j++) {
        float v = in[j];
#pragma unroll
        for (int c = 0; c < COUT; c++) acc[c] = fmaf(v, sW[j * COUT + c], acc[c]);
    }
#pragma unroll
    for (int c = 0; c < COUT; c++)
        y[((size_t)(b * COUT + c)) * (SS * KK) + rem] = acc[c];

    int lane = threadIdx.x & 31;
#pragma unroll
    for (int c = 0; c < COUT; c++) {
        float v = acc[c], v2 = v * v;
#pragma unroll
        for (int o = 16; o; o >>= 1) {
            v  += __shfl_down_sync(0xffffffffu, v,  o);
            v2 += __shfl_down_sync(0xffffffffu, v2, o);
        }
        if (lane == 0) { atomicAdd(&sum[b * 64 + c], v); atomicAdd(&sq[b * 64 + c], v2); }
    }
}

// ---------------- instance-norm + relu + 1x1 conv + stats ----------------
template <int CIN, int COUT, int SS>
__global__ void k_mm(const float* __restrict__ x, const float* __restrict__ W,
                     const float* __restrict__ sumIn, const float* __restrict__ sqIn,
                     float* __restrict__ y,
                     float* __restrict__ sumOut, float* __restrict__ sqOut)
{
    __shared__ float sW[CIN * COUT];
    __shared__ float sMu[CIN], sInv[CIN];
    int r = blockIdx.x * blockDim.x + threadIdx.x;
    int b = r / (SS * KK);
    int rem = r - b * (SS * KK);
    for (int i = threadIdx.x; i < CIN * COUT; i += blockDim.x) sW[i] = W[i];
    if (threadIdx.x < CIN) {
        float cnt = (float)(SS * KK);
        float mu = sumIn[b * 64 + threadIdx.x] / cnt;
        float var = sqIn[b * 64 + threadIdx.x] / cnt - mu * mu;
        sMu[threadIdx.x] = mu;
        sInv[threadIdx.x] = rsqrtf(var + 1e-5f);
    }
    __syncthreads();

    float acc[COUT];
#pragma unroll
    for (int c = 0; c < COUT; c++) acc[c] = 0.f;
#pragma unroll
    for (int j = 0; j < CIN; j++) {
        float v = x[((size_t)(b * CIN + j)) * (SS * KK) + rem];
        v = fmaxf(0.f, (v - sMu[j]) * sInv[j]);
#pragma unroll
        for (int c = 0; c < COUT; c++) acc[c] = fmaf(v, sW[j * COUT + c], acc[c]);
    }
#pragma unroll
    for (int c = 0; c < COUT; c++)
        y[((size_t)(b * COUT + c)) * (SS * KK) + rem] = acc[c];

    int lane = threadIdx.x & 31;
#pragma unroll
    for (int c = 0; c < COUT; c++) {
        float v = acc[c], v2 = v * v;
#pragma unroll
        for (int o = 16; o; o >>= 1) {
            v  += __shfl_down_sync(0xffffffffu, v,  o);
            v2 += __shfl_down_sync(0xffffffffu, v2, o);
        }
        if (lane == 0) { atomicAdd(&sumOut[b * 64 + c], v); atomicAdd(&sqOut[b * 64 + c], v2); }
    }
}

// ---------------- instance-norm + relu + maxpool over K ----------------
template <int C, int SS, bool CHMAJOR>
__global__ void k_maxpool(const float* __restrict__ x,
                          const float* __restrict__ sumIn, const float* __restrict__ sqIn,
                          float* __restrict__ outp)
{
    int t = blockIdx.x * blockDim.x + threadIdx.x;
    int s = t % SS;
    int c = (t / SS) % C;
    int b = t / (SS * C);
    float cnt = (float)(SS * KK);
    float mu = sumIn[b * 64 + c] / cnt;
    float var = sqIn[b * 64 + c] / cnt - mu * mu;
    float inv = rsqrtf(var + 1e-5f);

    const float4* p = reinterpret_cast<const float4*>(
        x + ((size_t)(b * C + c)) * (SS * KK) + (size_t)s * KK);
    float m = -3.4e38f;
#pragma unroll
    for (int qv = 0; qv < KK / 4; qv++) {
        float4 v = p[qv];
        m = fmaxf(m, fmaxf(fmaxf(v.x, v.y), fmaxf(v.z, v.w)));
    }
    float outv = fmaxf(0.f, (m - mu) * inv);
    if (CHMAJOR) outp[(b * C + c) * SS + s] = outv;
    else         outp[(b * SS + s) * C + c] = outv;
}

// ---------------- launch ----------------
extern "C" void kernel_launch(void* const* d_in, const int* in_sizes, int n_in,
                              void* d_out, int out_size)
{
    const float* pc     = (const float*)d_in[0];
    const float* feat   = (const float*)d_in[1];
    const float* sa1_w1 = (const float*)d_in[2];
    const float* sa1_w2 = (const float*)d_in[3];
    const float* sa1_w3 = (const float*)d_in[4];
    const float* sa2_w1 = (const float*)d_in[5];
    const float* sa2_w2 = (const float*)d_in[6];
    const float* sa2_w3 = (const float*)d_in[7];

    float* out = (float*)d_out;
    float* out_pc      = out;
    float* out_pc_l1   = out + 196608;
    float* out_pc_l2   = out + 196608 + 24576;
    float* out_feat_l2 = out + 196608 + 24576 + 12288;
    float* out_fidx1   = out + 196608 + 24576 + 12288 + 262144;
    float* out_fidx2   = out + 196608 + 24576 + 12288 + 262144 + 8192;

    float *xyz0, *feat0, *xyz1, *xyz2, *feat1, *bufA, *bufB, *sum, *sq;
    int *fidx1, *fidx2, *nidx1, *nidx2;
    cudaGetSymbolAddress((void**)&xyz0,  g_xyz0);
    cudaGetSymbolAddress((void**)&feat0, g_feat0);
    cudaGetSymbolAddress((void**)&xyz1,  g_xyz1);
    cudaGetSymbolAddress((void**)&xyz2,  g_xyz2);
    cudaGetSymbolAddress((void**)&feat1, g_feat1);
    cudaGetSymbolAddress((void**)&bufA,  g_bufA);
    cudaGetSymbolAddress((void**)&bufB,  g_bufB);
    cudaGetSymbolAddress((void**)&sum,   g_sum);
    cudaGetSymbolAddress((void**)&sq,    g_sq);
    cudaGetSymbolAddress((void**)&fidx1, g_fidx1);
    cudaGetSymbolAddress((void**)&fidx2, g_fidx2);
    cudaGetSymbolAddress((void**)&nidx1, g_nidx1);
    cudaGetSymbolAddress((void**)&nidx2, g_nidx2);

    cudaFuncSetAttribute((const void*)k_fps<N0, S1V, 512>,
                         cudaFuncAttributeMaxDynamicSharedMemorySize, 3 * N0 * 4);
    cudaFuncSetAttribute((const void*)k_fps<S1V, S2V, 512>,
                         cudaFuncAttributeMaxDynamicSharedMemorySize, 3 * S1V * 4);

    // one-time side stream + events (host objects only; no device allocation)
    static cudaStream_t s1 = nullptr;
    static cudaEvent_t evSeg[4], evPool1;
    if (!s1) {
        cudaStreamCreateWithFlags(&s1, cudaStreamNonBlocking);
        for (int i = 0; i < 4; i++) cudaEventCreateWithFlags(&evSeg[i], cudaEventDisableTiming);
        cudaEventCreateWithFlags(&evPool1, cudaEventDisableTiming);
    }

    k_zero<<<6, 256>>>();
    k_transpose<<<768, 256>>>(pc, feat, out_pc);

    // ---- FPS1 in 4 segments on the main stream; kNN1/gather1 chunks trail on s1 ----
    for (int seg = 0; seg < 4; seg++) {
        k_fps<N0, S1V, 512><<<BB, 512, 3 * N0 * 4>>>(
            xyz0, fidx1, xyz1, out_pc_l1, out_fidx1, seg * 512, (seg + 1) * 512);
        cudaEventRecord(evSeg[seg], 0);
    }
    for (int seg = 0; seg < 4; seg++) {
        cudaStreamWaitEvent(s1, evSeg[seg], 0);
        k_knn<N0, S1V, 2048><<<BB * 512 / 8, 256, 0, s1>>>(xyz1, xyz0, nidx1, seg * 512, 512);
        k_gather_mm<3, 32, S1V, N0><<<(BB * 512 * KK) / 256, 256, 0, s1>>>(
            xyz0, feat0, xyz1, nidx1, sa1_w1, bufA,
            sum + 0 * BB * 64, sq + 0 * BB * 64, seg * 512, 512);
    }
    // stage-1 MLP tail on s1
    k_mm<32, 32, S1V><<<(BB * S1V * KK) / 256, 256, 0, s1>>>(
        bufA, sa1_w2, sum + 0 * BB * 64, sq + 0 * BB * 64, bufB,
        sum + 1 * BB * 64, sq + 1 * BB * 64);
    k_mm<32, 32, S1V><<<(BB * S1V * KK) / 256, 256, 0, s1>>>(
        bufB, sa1_w3, sum + 1 * BB * 64, sq + 1 * BB * 64, bufA,
        sum + 2 * BB * 64, sq + 2 * BB * 64);
    k_maxpool<32, S1V, false><<<(BB * 32 * S1V) / 256, 256, 0, s1>>>(
        bufA, sum + 2 * BB * 64, sq + 2 * BB * 64, feat1);
    cudaEventRecord(evPool1, s1);

    // ---- FPS2 + kNN2 on main stream, concurrent with s1's MLP chain ----
    k_fps<S1V, S2V, 512><<<BB, 512, 3 * S1V * 4>>>(
        xyz1, fidx2, xyz2, out_pc_l2, out_fidx2, 0, S2V);
    k_knn<S1V, S2V, 2048><<<BB * S2V / 8, 256>>>(xyz2, xyz1, nidx2, 0, S2V);

    // ---- join, then stage-2 MLP on main stream ----
    cudaStreamWaitEvent(0, evPool1, 0);
    k_gather_mm<32, 64, S2V, S1V><<<(BB * S2V * KK) / 256, 256>>>(
        xyz1, feat1, xyz2, nidx2, sa2_w1, bufA,
        sum + 3 * BB * 64, sq + 3 * BB * 64, 0, S2V);
    k_mm<64, 64, S2V><<<(BB * S2V * KK) / 256, 256>>>(
        bufA, sa2_w2, sum + 3 * BB * 64, sq + 3 * BB * 64, bufB,
        sum + 4 * BB * 64, sq + 4 * BB * 64);
    k_mm<64, 64, S2V><<<(BB * S2V * KK) / 256, 256>>>(
        bufB, sa2_w3, sum + 4 * BB * 64, sq + 4 * BB * 64, bufA,
        sum + 5 * BB * 64, sq + 5 * BB * 64);
    k_maxpool<64, S2V, true><<<(BB * 64 * S2V) / 256, 256>>>(
        bufA, sum + 5 * BB * 64, sq + 5 * BB * 64, out_feat_l2);
}